// round 11
// baseline (speedup 1.0000x reference)
#include <cuda_runtime.h>

// y[b, i] = input[b, i] * diag(weight)[i] + bias[i]
// B = 8192, N = 4096, fp32.
//
// Kernel 1: gather diag(weight) -> __device__ scratch.
// Kernel 2: 256-bit streamer. Each thread: one ld.global.v8.f32 (32 B),
//   table lookup, 8 FMAs, one st.global.v8.f32. 16384 CTAs (best count
//   from R3-R10 sweep). Minimal instruction count per byte moved.

#define N_COLS 4096
#define N8 (N_COLS / 8)          // 512 float8 columns
#define THREADS 256

__device__ __align__(32) float g_diag[N_COLS];

struct f8 { float v[8]; };

__device__ __forceinline__ f8 ldg256(const float* p) {
    f8 r;
    asm volatile("ld.global.v8.f32 {%0,%1,%2,%3,%4,%5,%6,%7}, [%8];"
                 : "=f"(r.v[0]), "=f"(r.v[1]), "=f"(r.v[2]), "=f"(r.v[3]),
                   "=f"(r.v[4]), "=f"(r.v[5]), "=f"(r.v[6]), "=f"(r.v[7])
                 : "l"(p));
    return r;
}

__device__ __forceinline__ void stg256(float* p, const f8& r) {
    asm volatile("st.global.v8.f32 [%0], {%1,%2,%3,%4,%5,%6,%7,%8};"
                 :: "l"(p),
                    "f"(r.v[0]), "f"(r.v[1]), "f"(r.v[2]), "f"(r.v[3]),
                    "f"(r.v[4]), "f"(r.v[5]), "f"(r.v[6]), "f"(r.v[7])
                 : "memory");
}

__global__ void extract_diag_kernel(const float* __restrict__ weight, int n) {
    int i = blockIdx.x * blockDim.x + threadIdx.x;
    if (i < n) {
        g_diag[i] = weight[(size_t)i * (size_t)(n + 1)];
    }
}

__global__ void __launch_bounds__(THREADS)
scale_bias_kernel(const float* __restrict__ in,
                  const float* __restrict__ bias,
                  float* __restrict__ out) {
    int idx = blockIdx.x * THREADS + threadIdx.x;   // float8 index; exact grid
    int c   = idx & (N8 - 1);                       // float8 column

    f8 x = ldg256(in + (size_t)idx * 8);
    f8 d = ldg256(g_diag + (size_t)c * 8);          // 16 KB table, L1-resident
    f8 b = ldg256(bias + (size_t)c * 8);            // 16 KB table, L1-resident

    f8 y;
    #pragma unroll
    for (int k = 0; k < 8; k++) {
        y.v[k] = fmaf(x.v[k], d.v[k], b.v[k]);
    }
    stg256(out + (size_t)idx * 8, y);
}

extern "C" void kernel_launch(void* const* d_in, const int* in_sizes, int n_in,
                              void* d_out, int out_size) {
    const float* input  = (const float*)d_in[0];   // [B, N]
    const float* weight = (const float*)d_in[1];   // [N, N]
    const float* bias   = (const float*)d_in[2];   // [N]
    float* out = (float*)d_out;

    // 1) gather diagonal
    extract_diag_kernel<<<(N_COLS + 255) / 256, 256>>>(weight, N_COLS);

    // 2) 256-bit streamer: total8 = B*N/8 = 2^22, blocks = 16384.
    int total8 = out_size / 8;
    int blocks = total8 / THREADS;                 // 16384
    scale_bias_kernel<<<blocks, THREADS>>>(input, bias, out);
}